// round 17
// baseline (speedup 1.0000x reference)
#include <cuda_runtime.h>
#include <cuda_bf16.h>
#include <cuda_fp16.h>
#include <mma.h>
#include <cstdint>

using namespace nvcuda;

// Problem constants (fixed shapes for this problem instance).
#define NN 50000
#define DD 256
#define EE 400000

// ---------------- device scratch (no allocations allowed) ----------------
__device__ __half g_h16[NN * DD];               // h = feat @ Wsum (fp16, 25.6 MB, L2-resident)
__device__ __nv_bfloat16 g_ahi[NN * DD];        // feat split hi (25.6 MB)
__device__ __nv_bfloat16 g_alo[NN * DD];        // feat split lo (25.6 MB)
__device__ __nv_bfloat16 g_whi[DD * DD];        // Wsum split hi
__device__ __nv_bfloat16 g_wlo[DD * DD];        // Wsum split lo
__device__ int g_deg[3][NN];
__device__ int g_off[3][NN];
__device__ int g_cur[3][NN];
__device__ int g_csr[3][EE];

// ---------------- cp.async helpers ----------------
__device__ __forceinline__ void cp_async16(void* smem_dst, const void* gsrc) {
    uint32_t s = (uint32_t)__cvta_generic_to_shared(smem_dst);
    asm volatile("cp.async.cg.shared.global [%0], [%1], 16;" :: "r"(s), "l"(gsrc));
}
__device__ __forceinline__ void cp_commit() {
    asm volatile("cp.async.commit_group;");
}
template <int N>
__device__ __forceinline__ void cp_wait() {
    asm volatile("cp.async.wait_group %0;" :: "n"(N));
}

// ---------------- tiny kernels ----------------
__global__ void zero_kernel() {
    int i = blockIdx.x * blockDim.x + threadIdx.x;
    if (i < 3 * NN) {
        (&g_deg[0][0])[i] = 0;
        (&g_cur[0][0])[i] = 0;
    }
}

// Wsum = (W0+W1+W2)/3, split into bf16 hi + lo (residual).
__global__ void wsplit_kernel(const float* __restrict__ W0,
                              const float* __restrict__ W1,
                              const float* __restrict__ W2) {
    int i = blockIdx.x * blockDim.x + threadIdx.x;
    if (i < DD * DD) {
        float w = (W0[i] + W1[i] + W2[i]) * (1.0f / 3.0f);
        __nv_bfloat16 hi = __float2bfloat16(w);
        float r = w - __bfloat162float(hi);
        g_whi[i] = hi;
        g_wlo[i] = __float2bfloat16(r);
    }
}

// feat -> bf16 hi/lo split, vectorized float4.
__global__ void fsplit_kernel(const float* __restrict__ feat) {
    int i = blockIdx.x * blockDim.x + threadIdx.x;   // float4 index
    const int total4 = NN * DD / 4;
    if (i >= total4) return;
    float4 v = ((const float4*)feat)[i];
    __nv_bfloat16 h0 = __float2bfloat16(v.x);
    __nv_bfloat16 h1 = __float2bfloat16(v.y);
    __nv_bfloat16 h2 = __float2bfloat16(v.z);
    __nv_bfloat16 h3 = __float2bfloat16(v.w);
    __nv_bfloat16 l0 = __float2bfloat16(v.x - __bfloat162float(h0));
    __nv_bfloat16 l1 = __float2bfloat16(v.y - __bfloat162float(h1));
    __nv_bfloat16 l2 = __float2bfloat16(v.z - __bfloat162float(h2));
    __nv_bfloat16 l3 = __float2bfloat16(v.w - __bfloat162float(h3));
    __nv_bfloat162 hi01, hi23, lo01, lo23;
    hi01.x = h0; hi01.y = h1; hi23.x = h2; hi23.y = h3;
    lo01.x = l0; lo01.y = l1; lo23.x = l2; lo23.y = l3;
    ((__nv_bfloat162*)g_ahi)[i * 2 + 0] = hi01;
    ((__nv_bfloat162*)g_ahi)[i * 2 + 1] = hi23;
    ((__nv_bfloat162*)g_alo)[i * 2 + 0] = lo01;
    ((__nv_bfloat162*)g_alo)[i * 2 + 1] = lo23;
}

__global__ void deg_kernel(const int* __restrict__ d0,
                           const int* __restrict__ d1,
                           const int* __restrict__ d2, int E) {
    int i = blockIdx.x * blockDim.x + threadIdx.x;
    if (i >= 3 * E) return;
    int r = i / E;
    int e = i - r * E;
    const int* dp = (r == 0) ? d0 : (r == 1) ? d1 : d2;
    atomicAdd(&g_deg[r][dp[e]], 1);
}

// One block per relation: coalesced tiled scan (warp shuffles + carry).
__global__ __launch_bounds__(1024)
void scan_kernel(int n) {
    int r = blockIdx.x;
    int tid = threadIdx.x;
    int lane = tid & 31, wid = tid >> 5;
    const int* deg = g_deg[r];
    int* off = g_off[r];

    __shared__ int warpsum[32];
    __shared__ int s_carry;
    if (tid == 0) s_carry = 0;
    __syncthreads();

    for (int base = 0; base < n; base += 1024) {
        int idx = base + tid;
        int v = (idx < n) ? deg[idx] : 0;
        int x = v;
#pragma unroll
        for (int o = 1; o < 32; o <<= 1) {
            int t = __shfl_up_sync(0xFFFFFFFFu, x, o);
            if (lane >= o) x += t;
        }
        if (lane == 31) warpsum[wid] = x;
        __syncthreads();
        if (wid == 0) {
            int w = warpsum[lane];
#pragma unroll
            for (int o = 1; o < 32; o <<= 1) {
                int t = __shfl_up_sync(0xFFFFFFFFu, w, o);
                if (lane >= o) w += t;
            }
            warpsum[lane] = w;
        }
        __syncthreads();
        int carry = s_carry;
        int excl = carry + (wid ? warpsum[wid - 1] : 0) + x - v;
        if (idx < n) off[idx] = excl;
        __syncthreads();
        if (tid == 0) s_carry = carry + warpsum[31];
        __syncthreads();
    }
}

__global__ void fill_kernel(const int* __restrict__ s0, const int* __restrict__ d0,
                            const int* __restrict__ s1, const int* __restrict__ d1,
                            const int* __restrict__ s2, const int* __restrict__ d2,
                            int E) {
    int i = blockIdx.x * blockDim.x + threadIdx.x;
    if (i >= 3 * E) return;
    int r = i / E;
    int e = i - r * E;
    const int* sp = (r == 0) ? s0 : (r == 1) ? s1 : s2;
    const int* dp = (r == 0) ? d0 : (r == 1) ? d1 : d2;
    int dst = dp[e];
    int pos = g_off[r][dst] + atomicAdd(&g_cur[r][dst], 1);
    g_csr[r][pos] = sp[e];
}

// ---------------- split-bf16 tensor-core GEMM, cp.async double-buffered ------
// g_h16[M,256] = fp16( Ahi@Whi + Ahi@Wlo + Alo@Whi ) (fp32 accum), expressed
// as a single virtual K=768 loop: kt=0..23, term=kt/8, k0=(kt%8)*32, BK=32.
#define BK   32
#define LDA  40    // 32 + 8 pad (bf16 elems)
#define LDB  136   // 128 + 8 pad
#define KT_TOTAL 24

__global__ __launch_bounds__(256, 2)
void gemm_bf16_kernel(int M) {
    __shared__ __nv_bfloat16 As[2][128 * LDA];   // 2 x 10.0 KB
    __shared__ __nv_bfloat16 Bs[2][BK * LDB];    // 2 x 8.5 KB
    __shared__ float stage[8][16 * 16];          // per-warp fp32->fp16 staging, 8 KB

    int tid = threadIdx.x;
    int w = tid >> 5;
    int lane = tid & 31;
    int wm = w & 3;            // rows wm*32
    int wn = w >> 2;           // cols wn*64
    int rowBase = blockIdx.x * 128;
    int colBase = blockIdx.y * 128;

    wmma::fragment<wmma::accumulator, 16, 16, 16, float> c[2][4];
#pragma unroll
    for (int i = 0; i < 2; i++)
#pragma unroll
        for (int j = 0; j < 4; j++) wmma::fill_fragment(c[i][j], 0.0f);

    auto issue = [&](int s, int kt) {
        int t = kt >> 3;
        int k0 = (kt & 7) * BK;
        const __nv_bfloat16* Ap = (t < 2) ? g_ahi : g_alo;
        const __nv_bfloat16* Bp = (t == 1) ? g_wlo : g_whi;
#pragma unroll
        for (int l = 0; l < 2; l++) {
            int f = tid + l * 256;       // 0..511
            int ar = f >> 2;             // 0..127
            int ac = (f & 3) * 8;        // 0,8,16,24
            __nv_bfloat16* dst = &As[s][ar * LDA + ac];
            int grow = rowBase + ar;
            if (grow < M)
                cp_async16(dst, &Ap[(size_t)grow * DD + k0 + ac]);
            else
                *(uint4*)dst = make_uint4(0u, 0u, 0u, 0u);
        }
#pragma unroll
        for (int l = 0; l < 2; l++) {
            int f = tid + l * 256;       // 0..511
            int br = f >> 4;             // 0..31
            int bc = (f & 15) * 8;       // 0..120
            cp_async16(&Bs[s][br * LDB + bc],
                       &Bp[(size_t)(k0 + br) * DD + colBase + bc]);
        }
        cp_commit();
    };

    issue(0, 0);
    for (int kt = 0; kt < KT_TOTAL; kt++) {
        int s = kt & 1;
        if (kt + 1 < KT_TOTAL) {
            issue(s ^ 1, kt + 1);
            cp_wait<1>();                // current stage's group done; prefetch in flight
        } else {
            cp_wait<0>();
        }
        __syncthreads();

#pragma unroll
        for (int kk = 0; kk < 2; kk++) {
            wmma::fragment<wmma::matrix_a, 16, 16, 16, __nv_bfloat16, wmma::row_major> a[2];
            wmma::fragment<wmma::matrix_b, 16, 16, 16, __nv_bfloat16, wmma::row_major> b[4];
#pragma unroll
            for (int i = 0; i < 2; i++)
                wmma::load_matrix_sync(a[i], &As[s][(wm * 32 + i * 16) * LDA + kk * 16], LDA);
#pragma unroll
            for (int j = 0; j < 4; j++)
                wmma::load_matrix_sync(b[j], &Bs[s][(kk * 16) * LDB + wn * 64 + j * 16], LDB);
#pragma unroll
            for (int i = 0; i < 2; i++)
#pragma unroll
                for (int j = 0; j < 4; j++)
                    wmma::mma_sync(c[i][j], a[i], b[j], c[i][j]);
        }
        __syncthreads();                 // stage s reusable for kt+2's loads
    }

    // Store: per-warp staging tile -> fp16 global. Each 16x16 tile:
    // store fp32 to stage[w], then each lane writes 8 halves (one uint4).
    // M is a multiple of 16, so each 16-row tile is fully in or out.
#pragma unroll
    for (int i = 0; i < 2; i++) {
        int rowTile = rowBase + wm * 32 + i * 16;
        if (rowTile >= M) continue;
#pragma unroll
        for (int j = 0; j < 4; j++) {
            wmma::store_matrix_sync(stage[w], c[i][j], 16, wmma::mem_row_major);
            __syncwarp();
            int r = lane >> 1;               // 0..15
            int c0 = (lane & 1) * 8;         // 0 or 8
            const float* sp = &stage[w][r * 16 + c0];
            __half2 h2[4];
#pragma unroll
            for (int q = 0; q < 4; q++)
                h2[q] = __floats2half2_rn(sp[q * 2], sp[q * 2 + 1]);
            *(uint4*)&g_h16[(size_t)(rowTile + r) * DD + colBase + wn * 64 + j * 16 + c0] =
                *(uint4*)h2;
            __syncwarp();
        }
    }
}

// ---------------- gather + cross-relation mean + relu + LayerNorm ------------
// One block (256 threads) per destination node; thread t owns feature dim t.
// All 3 relations' edges staged into ONE combined (index, weight) list.
// Gathers fp16 h rows (half the L2 traffic of fp32).
__global__ __launch_bounds__(256)
void agg_ln_kernel(const float* __restrict__ gamma,
                   const float* __restrict__ beta,
                   float* __restrict__ out, int n) {
    int v = blockIdx.x;
    if (v >= n) return;
    int tid = threadIdx.x;

    __shared__ int   es[256];
    __shared__ float ws[256];

    int dg0 = g_deg[0][v], dg1 = g_deg[1][v], dg2 = g_deg[2][v];
    int o0 = g_off[0][v], o1 = g_off[1][v], o2 = g_off[2][v];
    int b1 = dg0, b2 = dg0 + dg1;
    int T = dg0 + dg1 + dg2;
    float w0 = dg0 ? 1.0f / (3.0f * (float)dg0) : 0.f;
    float w1 = dg1 ? 1.0f / (3.0f * (float)dg1) : 0.f;
    float w2 = dg2 ? 1.0f / (3.0f * (float)dg2) : 0.f;

    float acc = 0.f;
    for (int base = 0; base < T; base += 256) {
        int j = base + tid;
        int cnt = min(256, T - base);
        if (j < T) {
            int idx; float wt;
            if (j < b1)      { idx = g_csr[0][o0 + j];      wt = w0; }
            else if (j < b2) { idx = g_csr[1][o1 + j - b1]; wt = w1; }
            else             { idx = g_csr[2][o2 + j - b2]; wt = w2; }
            es[tid] = idx;
            ws[tid] = wt;
        }
        __syncthreads();
#pragma unroll 8
        for (int i = 0; i < cnt; i++)
            acc += __half2float(g_h16[(size_t)es[i] * DD + tid]) * ws[i];
        __syncthreads();
    }

    float x = fmaxf(acc, 0.f);

    float s1 = x, s2 = x * x;
#pragma unroll
    for (int o = 16; o > 0; o >>= 1) {
        s1 += __shfl_xor_sync(0xFFFFFFFFu, s1, o);
        s2 += __shfl_xor_sync(0xFFFFFFFFu, s2, o);
    }
    __shared__ float r1[8], r2[8];
    int wid = tid >> 5, lane = tid & 31;
    if (lane == 0) { r1[wid] = s1; r2[wid] = s2; }
    __syncthreads();
    s1 = 0.f; s2 = 0.f;
#pragma unroll
    for (int i = 0; i < 8; i++) { s1 += r1[i]; s2 += r2[i]; }

    float mean = s1 * (1.0f / 256.0f);
    float var = s2 * (1.0f / 256.0f) - mean * mean;
    var = fmaxf(var, 0.f);
    float inv = rsqrtf(var + 1e-5f);
    out[(size_t)v * DD + tid] = (x - mean) * inv * gamma[tid] + beta[tid];
}

// ---------------- launch ----------------
extern "C" void kernel_launch(void* const* d_in, const int* in_sizes, int n_in,
                              void* d_out, int out_size) {
    const float* feat  = (const float*)d_in[0];
    const float* W0    = (const float*)d_in[1];
    const float* W1    = (const float*)d_in[2];
    const float* W2    = (const float*)d_in[3];
    // d_in[4..6] = a0,a1,a2 : softmax over size-1 tensors -> exactly 1/3 weights; unused.
    const float* gamma = (const float*)d_in[7];
    const float* beta  = (const float*)d_in[8];
    const int* src0 = (const int*)d_in[9];
    const int* dst0 = (const int*)d_in[10];
    const int* src1 = (const int*)d_in[11];
    const int* dst1 = (const int*)d_in[12];
    const int* src2 = (const int*)d_in[13];
    const int* dst2 = (const int*)d_in[14];

    int N = in_sizes[0] / DD;     // 50000
    int E = in_sizes[9];          // 400000

    static cudaStream_t s_side = nullptr;
    static cudaEvent_t  ev_fork = nullptr, ev_join = nullptr;
    if (s_side == nullptr) {
        cudaStreamCreateWithFlags(&s_side, cudaStreamNonBlocking);
        cudaEventCreateWithFlags(&ev_fork, cudaEventDisableTiming);
        cudaEventCreateWithFlags(&ev_join, cudaEventDisableTiming);
    }

    // Fork: CSR-build chain runs on s_side, concurrent with the GEMM chain.
    cudaEventRecord(ev_fork, 0);
    cudaStreamWaitEvent(s_side, ev_fork, 0);

    // Branch B (side stream): CSR build
    zero_kernel<<<(3 * NN + 255) / 256, 256, 0, s_side>>>();
    deg_kernel<<<(3 * E + 255) / 256, 256, 0, s_side>>>(dst0, dst1, dst2, E);
    scan_kernel<<<3, 1024, 0, s_side>>>(N);
    fill_kernel<<<(3 * E + 255) / 256, 256, 0, s_side>>>(src0, dst0, src1, dst1,
                                                         src2, dst2, E);
    cudaEventRecord(ev_join, s_side);

    // Branch A (main stream): weight split + feat split + tensor-core GEMM
    wsplit_kernel<<<(DD * DD + 255) / 256, 256>>>(W0, W1, W2);
    fsplit_kernel<<<(NN * DD / 4 + 255) / 256, 256>>>(feat);
    dim3 ggrid((N + 127) / 128, DD / 128);
    gemm_bf16_kernel<<<ggrid, 256>>>(N);

    // Join: agg needs both g_h16 (branch A) and the CSR (branch B).
    cudaStreamWaitEvent(0, ev_join, 0);
    agg_ln_kernel<<<N, 256>>>(gamma, beta, (float*)d_out, N);
}